// round 16
// baseline (speedup 1.0000x reference)
#include <cuda_runtime.h>
#include <math.h>

// Shapes fixed by the problem instance
#define KB    4
#define CIN   8
#define COUT  64
#define NLEN  4096
#define NROWS (KB * CIN)      // 32 input rows
#define SPLIT 2               // DFT blocks per input row (half-rows)
#define NPROD (NROWS * SPLIT) // 64 producer blocks
#define NB    (KB * COUT)     // 256 output rows
#define NBLK  256             // total grid == NB (all arrive; snapshot-safe)
#define TWO_PI_OVER_N 0.0015339807878856412f   // 2*pi/4096

// Scratch
__device__ float    g_part_r[NROWS][SPLIT];
__device__ float    g_part_i[NROWS][SPLIT];
__device__ int      g_count = 0;
__device__ unsigned g_flag  = 0;   // generation counter

// Per-thread output phasors e^{i*omega*mu}, mu = j*1024 + tid*4 + l,
// computed with 3 exact-index sincosf + 15 complex rotations.
__device__ __forceinline__ void compute_phases(int m, int tid,
                                               float* __restrict__ pc,
                                               float* __restrict__ ps)
{
    float bc, bs, c1, s1, cJ, sJ;
    {
        const int p0 = (m * (tid * 4)) & (NLEN - 1);
        __sincosf(TWO_PI_OVER_N * (float)p0, &bs, &bc);
        const int p1 = m & (NLEN - 1);
        __sincosf(TWO_PI_OVER_N * (float)p1, &s1, &c1);
        const int pJ = (m * 1024) & (NLEN - 1);
        __sincosf(TWO_PI_OVER_N * (float)pJ, &sJ, &cJ);
    }
    float cj = bc, sj = bs;
#pragma unroll
    for (int j = 0; j < 4; j++) {
        float cc = cj, ss = sj;
#pragma unroll
        for (int l = 0; l < 4; l++) {
            pc[j * 4 + l] = cc;
            ps[j * 4 + l] = ss;
            const float cn = cc * c1 - ss * s1;   // rotate by e^{i*omega}
            const float sn = cc * s1 + ss * c1;
            cc = cn; ss = sn;
        }
        const float cn = cj * cJ - sj * sJ;       // rotate by e^{i*omega*1024}
        const float sn = cj * sJ + sj * cJ;
        cj = cn; sj = sn;
    }
}

__global__ __launch_bounds__(256) void fused_kernel(
    const float* __restrict__ zr, const float* __restrict__ zi,
    const float* __restrict__ A, const float* __restrict__ beta,
    const float* __restrict__ bias, const int* __restrict__ mptr,
    float* __restrict__ out)
{
    const int tid  = threadIdx.x;
    const int bx   = blockIdx.x;
    const int lane = tid & 31;
    const bool producer = (bx < NPROD);

    __shared__ float swr[8], swi[8];

    // tid-0 snapshot of the generation BEFORE this block's own arrival.
    unsigned my_init = 0;
    if (tid == 0) my_init = *((volatile unsigned*)&g_flag);

    const int m = *mptr;

    // ---- Pre-barrier W hoist for this block's output row ----
    const int k  = bx >> 6;
    const int co = bx & 63;
    const int ci = lane & 7;
    const int sp = (lane >> 3) & 1;
    float Wr, Wi;
    {
        const float a = fabsf(A[co * CIN + ci]);
        float sb, cb;
        __sincosf(beta[co * CIN + ci], &sb, &cb);
        Wr = a * cb; Wi = a * sb;
    }
    const float bco = bias[co];

    // ---------------- Phase A (producers only) ----------------
    if (producer) {
        const int b     = bx >> 1;
        const int split = bx & 1;
        const int base  = split * 2048 + tid * 8;
        const float* pr = zr + (size_t)b * NLEN + base;
        const float* pi = zi + (size_t)b * NLEN + base;

        const float4 xa = *reinterpret_cast<const float4*>(pr);
        const float4 xb = *reinterpret_cast<const float4*>(pr + 4);
        const float4 ya = *reinterpret_cast<const float4*>(pi);
        const float4 yb = *reinterpret_cast<const float4*>(pi + 4);
        const float xs[8] = {xa.x, xa.y, xa.z, xa.w, xb.x, xb.y, xb.z, xb.w};
        const float ys[8] = {ya.x, ya.y, ya.z, ya.w, yb.x, yb.y, yb.z, yb.w};

        // 2 sincosf + 7 complex rotations (exact phase indices).
        float s0, c0, s1, c1;
        {
            const int p0 = (m * base) & (NLEN - 1);
            __sincosf(TWO_PI_OVER_N * (float)p0, &s0, &c0);
            const int p1 = m & (NLEN - 1);
            __sincosf(TWO_PI_OVER_N * (float)p1, &s1, &c1);
        }

        float ar = 0.f, ai = 0.f;
        float c = c0, s = s0;
#pragma unroll
        for (int j = 0; j < 8; j++) {
            ar += xs[j] * c - ys[j] * s;               // e^{+i*omega*t} * z
            ai += xs[j] * s + ys[j] * c;
            const float cn = c * c1 - s * s1;          // rotate by e^{i*omega}
            const float sn = c * s1 + s * c1;
            c = cn; s = sn;
        }

#pragma unroll
        for (int off = 16; off > 0; off >>= 1) {
            ar += __shfl_down_sync(0xffffffff, ar, off);
            ai += __shfl_down_sync(0xffffffff, ai, off);
        }
        if (lane == 0) { swr[tid >> 5] = ar; swi[tid >> 5] = ai; }
        __syncthreads();
        if (tid == 0) {
            float tr = 0.f, ti = 0.f;
#pragma unroll
            for (int w = 0; w < 8; w++) { tr += swr[w]; ti += swi[w]; }
            g_part_r[b][split] = tr;
            g_part_i[b][split] = ti;
        }
    }

    // ---- Consumers: compute output phasors now (hidden under producer DFT) ----
    float pc[16], ps[16];
    if (!producer) compute_phases(m, tid, pc, ps);

    // ------------- Grid barrier: all 256 arrive, last releases -------------
    if (tid == 0) {
        __threadfence();                        // publish partials
        int old = atomicAdd(&g_count, 1);
        if (old == NBLK - 1) {
            atomicExch(&g_count, 0);            // reset for next graph replay
            atomicAdd(&g_flag, 1);              // release
        }
    }

    // ---- Producers: compute phasors during the spin window ----
    if (producer) compute_phases(m, tid, pc, ps);

    if (tid == 0) {
        while (*((volatile unsigned*)&g_flag) == my_init) { }
    }
    __syncthreads();
    __threadfence();                            // acquire partials

    // ------------- Warp-redundant G: all lanes end with G -------------
    float Gr, Gi;
    {
        const int row = k * CIN + ci;
        const float Zr = g_part_r[row][sp];
        const float Zi = g_part_i[row][sp];
        Gr = Wr * Zr - Wi * Zi;
        Gi = Wr * Zi + Wi * Zr;
#pragma unroll
        for (int off = 1; off < 16; off <<= 1) {
            Gr += __shfl_xor_sync(0xffffffff, Gr, off);
            Gi += __shfl_xor_sync(0xffffffff, Gi, off);
        }
    }
    const float mag  = sqrtf(Gr * Gr + Gi * Gi);
    const float gate = (1.f / (1.f + __expf(-(mag + bco)))) / (mag + 1e-5f);
    const float gr = gate * Gr;
    const float gi = gate * Gi;

    // ---------------- Phase B: pure FFMA + stores (no loads) ----------------
    float* outr = out + (size_t)bx * NLEN;
    float* outi = out + (size_t)NB * NLEN + (size_t)bx * NLEN;

#pragma unroll
    for (int j = 0; j < 4; j++) {
        const int mu0 = j * 1024 + tid * 4;
        float4 vr, vi;
        vr.x = gr * pc[j*4+0] + gi * ps[j*4+0];  vi.x = gi * pc[j*4+0] - gr * ps[j*4+0];
        vr.y = gr * pc[j*4+1] + gi * ps[j*4+1];  vi.y = gi * pc[j*4+1] - gr * ps[j*4+1];
        vr.z = gr * pc[j*4+2] + gi * ps[j*4+2];  vi.z = gi * pc[j*4+2] - gr * ps[j*4+2];
        vr.w = gr * pc[j*4+3] + gi * ps[j*4+3];  vi.w = gi * pc[j*4+3] - gr * ps[j*4+3];

        *reinterpret_cast<float4*>(outr + mu0) = vr;
        *reinterpret_cast<float4*>(outi + mu0) = vi;
    }
}

extern "C" void kernel_launch(void* const* d_in, const int* in_sizes, int n_in,
                              void* d_out, int out_size)
{
    const float* z_real = (const float*)d_in[0];
    const float* z_imag = (const float*)d_in[1];
    const float* A      = (const float*)d_in[2];
    const float* beta   = (const float*)d_in[3];
    const float* bias   = (const float*)d_in[4];
    const int*   mptr   = (const int*)d_in[5];
    float* out = (float*)d_out;

    fused_kernel<<<NBLK, 256>>>(z_real, z_imag, A, beta, bias, mptr, out);
}